// round 1
// baseline (speedup 1.0000x reference)
#include <cuda_runtime.h>

#define BB 512
#define DD 1024
#define HH 512
#define CC 4
#define DCH 16              // d-chunk size
#define KK (DD / DCH)       // 64 chunks

// P[k][h][b] : prefix of (c + sum_{j<k*DCH} x[b,j]*W[h,j])
__device__ float g_P[(size_t)KK * HH * BB];   // 67 MB scratch

__device__ __forceinline__ float sigmoid_fast(float a) {
    float e = __expf(-a);           // FMUL + MUFU.EX2
    float t = 1.0f + e;             // FADD
    float r;
    asm("rcp.approx.f32 %0, %1;" : "=f"(r) : "f"(t));   // MUFU.RCP
    return r;
}

// ---------------- Phase 1: chunked prefix GEMM ----------------
// grid (HH/16, BB/64), block 256.
// Thread: b_local = tid&63 (one b), h_group = tid>>6, handles 4 h's: h0+hg+4m.
__global__ __launch_bounds__(256) void nade_phase1(
    const float* __restrict__ x, const float* __restrict__ W,
    const float* __restrict__ cvec)
{
    __shared__ float xs[DCH][64];   // xs[jj][b_local]
    __shared__ float ws[DCH][16];   // ws[jj][h_local]

    const int h0 = blockIdx.x * 16;
    const int b0 = blockIdx.y * 64;
    const int tid = threadIdx.x;
    const int bl = tid & 63;
    const int hg = tid >> 6;        // 0..3

    float acc[4];
#pragma unroll
    for (int m = 0; m < 4; m++) acc[m] = __ldg(&cvec[h0 + hg + 4 * m]);

    for (int j = 0; j < DD; j += DCH) {
        const int k = j / DCH;
        // write exclusive prefix for chunk k (before adding this tile)
#pragma unroll
        for (int m = 0; m < 4; m++)
            g_P[((size_t)k * HH + (h0 + hg + 4 * m)) * BB + b0 + bl] = acc[m];

        __syncthreads();   // protect smem from prior-iteration readers
        if (tid < 64) {
            const float4* xrow = (const float4*)(x + (size_t)(b0 + tid) * DD + j);
#pragma unroll
            for (int q = 0; q < 4; q++) {
                float4 v = __ldg(&xrow[q]);
                xs[4 * q + 0][tid] = v.x; xs[4 * q + 1][tid] = v.y;
                xs[4 * q + 2][tid] = v.z; xs[4 * q + 3][tid] = v.w;
            }
        } else if (tid < 128) {
            int t = tid - 64;
            int hh = t >> 2;          // 0..15
            int q = t & 3;            // 0..3
            float4 v = __ldg((const float4*)(W + (size_t)(h0 + hh) * DD + j) + q);
            ws[4 * q + 0][hh] = v.x; ws[4 * q + 1][hh] = v.y;
            ws[4 * q + 2][hh] = v.z; ws[4 * q + 3][hh] = v.w;
        }
        __syncthreads();

#pragma unroll
        for (int jj = 0; jj < DCH; jj++) {
            float xv = xs[jj][bl];
#pragma unroll
            for (int m = 0; m < 4; m++)
                acc[m] = fmaf(xv, ws[jj][hg + 4 * m], acc[m]);
        }
    }
}

// ---------------- Phase 2: per-chunk sequential NADE ----------------
// grid (KK, BB/64), block 128. tid -> bl = tid&63 (b), hseg = tid>>6 (H half).
__global__ __launch_bounds__(128) void nade_phase2(
    const float* __restrict__ x, const float* __restrict__ V,
    const float* __restrict__ bias, const float* __restrict__ W,
    float* __restrict__ out)
{
    __shared__ float red[DCH * CC][64];   // [d*C+c][b_local], conflict-free

    const int k = blockIdx.x;
    const int b0 = blockIdx.y * 64;
    const int tid = threadIdx.x;
    const int bl = tid & 63;
    const int hseg = tid >> 6;
    const int b = b0 + bl;
    const int d0 = k * DCH;

    // preload x[b, d0:d0+16]
    float xv[DCH];
    {
        const float4* xr = (const float4*)(x + (size_t)b * DD + d0);
#pragma unroll
        for (int q = 0; q < DCH / 4; q++) {
            float4 v = __ldg(&xr[q]);
            xv[4 * q + 0] = v.x; xv[4 * q + 1] = v.y;
            xv[4 * q + 2] = v.z; xv[4 * q + 3] = v.w;
        }
    }

    float acc[DCH][CC];
#pragma unroll
    for (int d = 0; d < DCH; d++)
#pragma unroll
        for (int c = 0; c < CC; c++) acc[d][c] = 0.0f;

    const int hstart = hseg * (HH / 2);
    const float* Pk = g_P + (size_t)k * HH * BB;

    for (int h = hstart; h < hstart + HH / 2; h++) {
        float a = __ldg(&Pk[(size_t)h * BB + b]);                 // coalesced
        const float4* wr = (const float4*)(W + (size_t)h * DD + d0);
        const float4* vr = (const float4*)(V + ((size_t)h * DD + d0) * CC);
#pragma unroll
        for (int q = 0; q < DCH / 4; q++) {
            float4 w4 = __ldg(&wr[q]);
            float wq[4] = {w4.x, w4.y, w4.z, w4.w};
#pragma unroll
            for (int r = 0; r < 4; r++) {
                const int d = 4 * q + r;
                float4 v = __ldg(&vr[d]);                         // broadcast in warp
                float hv = sigmoid_fast(a);
                acc[d][0] = fmaf(hv, v.x, acc[d][0]);
                acc[d][1] = fmaf(hv, v.y, acc[d][1]);
                acc[d][2] = fmaf(hv, v.z, acc[d][2]);
                acc[d][3] = fmaf(hv, v.w, acc[d][3]);
                a = fmaf(xv[d], wq[r], a);                        // prefix advance
            }
        }
    }

    // combine H-segment partials (once per chunk, not per d)
    if (hseg == 1) {
#pragma unroll
        for (int d = 0; d < DCH; d++)
#pragma unroll
            for (int c = 0; c < CC; c++)
                red[d * CC + c][bl] = acc[d][c];
    }
    __syncthreads();

    if (hseg == 0) {
        float* yout = out + (size_t)b * (DD * CC) + (size_t)d0 * CC;
        float* pout = yout + (size_t)BB * DD * CC;
#pragma unroll
        for (int d = 0; d < DCH; d++) {
            float l[4];
#pragma unroll
            for (int c = 0; c < CC; c++)
                l[c] = acc[d][c] + red[d * CC + c][bl] + __ldg(&bias[(d0 + d) * CC + c]);

            float4 y4 = make_float4(l[0], l[1], l[2], l[3]);
            *(float4*)(yout + d * CC) = y4;

            float m = fmaxf(fmaxf(l[0], l[1]), fmaxf(l[2], l[3]));
            float s = __expf(l[0] - m) + __expf(l[1] - m) +
                      __expf(l[2] - m) + __expf(l[3] - m);
            float lse = m + __logf(s);
            float4 p4 = make_float4(l[0] - lse, l[1] - lse, l[2] - lse, l[3] - lse);
            *(float4*)(pout + d * CC) = p4;
        }
    }
}

extern "C" void kernel_launch(void* const* d_in, const int* in_sizes, int n_in,
                              void* d_out, int out_size) {
    const float* x    = (const float*)d_in[0];
    const float* V    = (const float*)d_in[1];
    const float* bias = (const float*)d_in[2];
    const float* W    = (const float*)d_in[3];
    const float* cvec = (const float*)d_in[4];
    float* out = (float*)d_out;

    nade_phase1<<<dim3(HH / 16, BB / 64), 256>>>(x, W, cvec);
    nade_phase2<<<dim3(KK, BB / 64), 128>>>(x, V, bias, W, out);
}